// round 1
// baseline (speedup 1.0000x reference)
#include <cuda_runtime.h>
#include <math.h>

// Problem constants (fixed by setup_inputs)
#define Bb    2
#define SS    1024
#define DD    1024
#define HH    16
#define DK    64
#define MM    8192
#define TOPK  32
#define BSr   (Bb*SS)        // 2048 token rows
#define NQ    (Bb*HH*SS)     // 32768 flat queries
#define CHUNK 2048
#define NCHUNK (NQ/CHUNK)    // 16

// ---------------- scratch (device globals; no allocation) ----------------
__device__ float g_q[NQ*DK];        // [B,H,S,dk]
__device__ float g_k[NQ*DK];
__device__ float g_v[NQ*DK];
__device__ float g_actx[BSr*DD];    // attention context [B,S,D]
__device__ float g_aproj[BSr*DD];   // attn_out @ Wo^T + bo
__device__ float g_mctx[BSr*DD];    // memory context [B,S,D]
__device__ float g_normq[NQ*DK];
__device__ float g_normk[MM*DK];
__device__ float g_sims[(long)CHUNK*MM];  // 64MB, reused per chunk (L2-resident)

#define BUF_Q     0
#define BUF_K     1
#define BUF_V     2
#define BUF_ACTX  3
#define BUF_APROJ 4
#define BUF_MCTX  5
#define BUF_NORMQ 6
#define BUF_NORMK 7
#define BUF_SIMS  8

__device__ __forceinline__ float* gbuf(int id) {
    switch (id) {
        case BUF_Q:     return g_q;
        case BUF_K:     return g_k;
        case BUF_V:     return g_v;
        case BUF_ACTX:  return g_actx;
        case BUF_APROJ: return g_aproj;
        case BUF_MCTX:  return g_mctx;
        case BUF_NORMQ: return g_normq;
        case BUF_NORMK: return g_normk;
        case BUF_SIMS:  return g_sims;
    }
    return nullptr;
}

// ---------------- SGEMM: C[r,c] = sum_k A[r,k] * W[c,k]  (+ epilogue) ----
// MODE 0: scatter-store to [B,H,S,dk] layout, + bias
// MODE 1: row-major store, + bias
// MODE 2: row-major: out = g*(acc+bias) + (1-g)*add   (g = sigmoid(gate))
// MODE 3: row-major plain store (sims)
#define GBM 128
#define GBN 64
#define GBK 16

template<int MODE>
__global__ __launch_bounds__(256)
void sgemm_nt(const float* __restrict__ Aext, int Aid, long Aoff,
              const float* __restrict__ Wext, int Wid,
              const float* __restrict__ bias,
              float* __restrict__ Cext, int Cid,
              int Nc, int Kd,
              int addid, const float* __restrict__ gatep)
{
    const float* A = (Aext ? Aext : gbuf(Aid)) + Aoff;
    const float* W = Wext ? Wext : gbuf(Wid);
    float* C = Cext ? Cext : gbuf(Cid);

    __shared__ __align__(16) float As[GBK][GBM + 4];   // row stride 528B (16B mult)
    __shared__ __align__(16) float Ws[GBK][GBN + 4];   // row stride 272B (16B mult)

    const int tid = threadIdx.x;
    const int rb = blockIdx.y * GBM;
    const int cb = blockIdx.x * GBN;
    const int lr = tid >> 2;            // 0..63
    const int lk = (tid & 3) << 2;      // 0,4,8,12
    const int ty = tid >> 4;            // 0..15
    const int tx = tid & 15;            // 0..15

    float acc[8][4];
#pragma unroll
    for (int i = 0; i < 8; i++)
#pragma unroll
        for (int j = 0; j < 4; j++) acc[i][j] = 0.f;

    for (int kb = 0; kb < Kd; kb += GBK) {
        float4 a0 = *(const float4*)(A + (long)(rb + lr)      * Kd + kb + lk);
        float4 a1 = *(const float4*)(A + (long)(rb + lr + 64) * Kd + kb + lk);
        float4 w0 = *(const float4*)(W + (long)(cb + lr)      * Kd + kb + lk);
        As[lk+0][lr]    = a0.x; As[lk+1][lr]    = a0.y; As[lk+2][lr]    = a0.z; As[lk+3][lr]    = a0.w;
        As[lk+0][lr+64] = a1.x; As[lk+1][lr+64] = a1.y; As[lk+2][lr+64] = a1.z; As[lk+3][lr+64] = a1.w;
        Ws[lk+0][lr]    = w0.x; Ws[lk+1][lr]    = w0.y; Ws[lk+2][lr]    = w0.z; Ws[lk+3][lr]    = w0.w;
        __syncthreads();
#pragma unroll
        for (int kk = 0; kk < GBK; kk++) {
            float4 av0 = *(const float4*)&As[kk][ty * 8];
            float4 av1 = *(const float4*)&As[kk][ty * 8 + 4];
            float4 bv  = *(const float4*)&Ws[kk][tx * 4];
            float a[8] = {av0.x, av0.y, av0.z, av0.w, av1.x, av1.y, av1.z, av1.w};
            float b[4] = {bv.x, bv.y, bv.z, bv.w};
#pragma unroll
            for (int i = 0; i < 8; i++)
#pragma unroll
                for (int j = 0; j < 4; j++)
                    acc[i][j] = fmaf(a[i], b[j], acc[i][j]);
        }
        __syncthreads();
    }

    float g = 0.f;
    if (MODE == 2) g = 1.f / (1.f + __expf(-gatep[0]));
    const float* add = (MODE == 2) ? gbuf(addid) : nullptr;

#pragma unroll
    for (int i = 0; i < 8; i++) {
        int r = rb + ty * 8 + i;
#pragma unroll
        for (int j = 0; j < 4; j++) {
            int c = cb + tx * 4 + j;
            float val = acc[i][j];
            if (MODE == 0) {
                int b_ = r >> 10, s_ = r & (SS - 1);
                int h_ = c >> 6,  d_ = c & 63;
                C[(((long)(b_ * HH + h_) * SS + s_) << 6) + d_] = val + bias[c];
            } else if (MODE == 1) {
                C[(long)r * Nc + c] = val + bias[c];
            } else if (MODE == 2) {
                C[(long)r * Nc + c] = g * (val + bias[c]) + (1.f - g) * add[(long)r * Nc + c];
            } else {
                C[(long)r * Nc + c] = val;
            }
        }
    }
}

// ---------------- causal attention: 4 queries per block --------------------
// grid: (S/4, B*H), 128 threads. Scores for 4 queries kept in shared (float4/key).
__global__ __launch_bounds__(128)
void attn_kernel()
{
    const int bh = blockIdx.y;           // 0..31
    const int s0 = blockIdx.x * 4;
    const int b_ = bh >> 4, h_ = bh & 15;
    const int tid = threadIdx.x;
    const int Lmax = s0 + 4;

    __shared__ __align__(16) float4 sc[SS];      // per-key probs for q0..q3
    __shared__ __align__(16) float  qs[4][DK];
    __shared__ float invs[4];
    __shared__ float pacc[4][DK];

    // phase 1: load 4 query rows
    for (int idx = tid; idx < 4 * DK; idx += 128) {
        int i = idx >> 6, d = idx & 63;
        qs[i][d] = g_q[(((long)bh * SS + s0 + i) << 6) + d];
    }
    __syncthreads();

    // phase 2: scores (each thread owns keys j = tid, tid+128, ...)
    const float scale = 0.125f;  // 1/sqrt(64)
    for (int j = tid; j < Lmax; j += 128) {
        const float4* kr = (const float4*)(g_k + (((long)bh * SS + j) << 6));
        float d0 = 0.f, d1 = 0.f, d2 = 0.f, d3 = 0.f;
#pragma unroll
        for (int c4 = 0; c4 < 16; c4++) {
            float4 kv = kr[c4];
            float4 q0 = *(const float4*)&qs[0][c4 * 4];
            float4 q1 = *(const float4*)&qs[1][c4 * 4];
            float4 q2 = *(const float4*)&qs[2][c4 * 4];
            float4 q3 = *(const float4*)&qs[3][c4 * 4];
            d0 += kv.x*q0.x + kv.y*q0.y + kv.z*q0.z + kv.w*q0.w;
            d1 += kv.x*q1.x + kv.y*q1.y + kv.z*q1.z + kv.w*q1.w;
            d2 += kv.x*q2.x + kv.y*q2.y + kv.z*q2.z + kv.w*q2.w;
            d3 += kv.x*q3.x + kv.y*q3.y + kv.z*q3.z + kv.w*q3.w;
        }
        sc[j] = make_float4(d0 * scale, d1 * scale, d2 * scale, d3 * scale);
    }
    __syncthreads();

    // phase 3: warp w does softmax for query w (causal length L = s0+w+1)
    {
        const int w = tid >> 5, lane = tid & 31;
        const int L = s0 + w + 1;
        float m = -1e30f;
        for (int j = lane; j < L; j += 32)
            m = fmaxf(m, ((const float*)&sc[j])[w]);
#pragma unroll
        for (int off = 16; off; off >>= 1)
            m = fmaxf(m, __shfl_xor_sync(0xffffffffu, m, off));
        float ssum = 0.f;
        for (int j = lane; j < L; j += 32) {
            float* p = &((float*)&sc[j])[w];
            float e = __expf(*p - m);
            *p = e;
            ssum += e;
        }
#pragma unroll
        for (int off = 16; off; off >>= 1)
            ssum += __shfl_xor_sync(0xffffffffu, ssum, off);
        if (lane == 0) invs[w] = 1.f / ssum;
        for (int j = L + lane; j < Lmax; j += 32)   // zero masked tail
            ((float*)&sc[j])[w] = 0.f;
    }
    __syncthreads();

    // phase 4: P @ V (thread = (half, d); lanes coalesced over d)
    const int d = tid & 63, half = tid >> 6;
    float a0 = 0.f, a1 = 0.f, a2 = 0.f, a3 = 0.f;
    for (int j = half; j < Lmax; j += 2) {
        float vv = g_v[(((long)bh * SS + j) << 6) + d];
        float4 p = sc[j];
        a0 = fmaf(p.x, vv, a0);
        a1 = fmaf(p.y, vv, a1);
        a2 = fmaf(p.z, vv, a2);
        a3 = fmaf(p.w, vv, a3);
    }
    if (half == 1) { pacc[0][d] = a0; pacc[1][d] = a1; pacc[2][d] = a2; pacc[3][d] = a3; }
    __syncthreads();
    if (half == 0) {
        a0 += pacc[0][d]; a1 += pacc[1][d]; a2 += pacc[2][d]; a3 += pacc[3][d];
        long base = ((long)(b_ * SS + s0)) * DD + h_ * 64 + d;
        g_actx[base]          = a0 * invs[0];
        g_actx[base +   DD]   = a1 * invs[1];
        g_actx[base + 2*DD]   = a2 * invs[2];
        g_actx[base + 3*DD]   = a3 * invs[3];
    }
}

// ---------------- row L2-normalization: v / (||v|| + 1e-8) -----------------
__global__ __launch_bounds__(256)
void normalize_rows(const float* __restrict__ ext, int srcid, int dstid, int rows)
{
    const float* src = ext ? ext : gbuf(srcid);
    float* dst = gbuf(dstid);
    int row = blockIdx.x * 8 + (threadIdx.x >> 5);
    int lane = threadIdx.x & 31;
    if (row >= rows) return;
    float e0 = src[(long)row * DK + lane];
    float e1 = src[(long)row * DK + lane + 32];
    float ss = e0 * e0 + e1 * e1;
#pragma unroll
    for (int off = 16; off; off >>= 1)
        ss += __shfl_xor_sync(0xffffffffu, ss, off);
    float sc = 1.f / (sqrtf(ss) + 1e-8f);
    dst[(long)row * DK + lane]      = e0 * sc;
    dst[(long)row * DK + lane + 32] = e1 * sc;
}

// ---------------- top-K selection + weighted gather ------------------------
// One block per query of the current chunk. sims row comes from L2-resident scratch.
__global__ __launch_bounds__(256)
void topk_kernel(const float* __restrict__ mem_vals, int chunk)
{
    const int qloc = blockIdx.x;
    const int qidx = chunk * CHUNK + qloc;
    const int tid = threadIdx.x;
    const int lane = tid & 31, wid = tid >> 5;

    __shared__ __align__(16) float sims_s[MM];   // 32KB
    __shared__ float wmax[8];
    __shared__ int   widx[8];
    __shared__ float bs_s;
    __shared__ int   bi_s;

    const float4* src = (const float4*)(g_sims + (long)qloc * MM);
    for (int m4 = tid; m4 < MM / 4; m4 += 256)
        ((float4*)sims_s)[m4] = src[m4];
    __syncthreads();

    // per-thread local max over its 32 strided slots (owner(m) = m & 255)
    float lb = -1e30f; int li = -1;
#pragma unroll
    for (int i = 0; i < MM / 256; i++) {
        int m = tid + i * 256;
        float v = sims_s[m];
        if (v > lb) { lb = v; li = m; }
    }

    float acc = 0.f;
    for (int t = 0; t < TOPK; t++) {
        // warp argmax
        float bv = lb; int bi = li;
#pragma unroll
        for (int off = 16; off; off >>= 1) {
            float ov = __shfl_xor_sync(0xffffffffu, bv, off);
            int   oi = __shfl_xor_sync(0xffffffffu, bi, off);
            if (ov > bv || (ov == bv && oi < bi)) { bv = ov; bi = oi; }
        }
        if (lane == 0) { wmax[wid] = bv; widx[wid] = bi; }
        __syncthreads();
        if (wid == 0) {
            float v2 = (lane < 8) ? wmax[lane] : -1e30f;
            int   i2 = (lane < 8) ? widx[lane] : 0x7fffffff;
#pragma unroll
            for (int off = 4; off; off >>= 1) {
                float ov = __shfl_xor_sync(0xffffffffu, v2, off);
                int   oi = __shfl_xor_sync(0xffffffffu, i2, off);
                if (ov > v2 || (ov == v2 && oi < i2)) { v2 = ov; i2 = oi; }
            }
            if (lane == 0) { bs_s = v2; bi_s = i2; }
        }
        __syncthreads();
        float bsv = bs_s; int biv = bi_s;
        if (tid < DK)
            acc = fmaf(bsv, mem_vals[(long)biv * DK + tid], acc);
        if ((biv & 255) == tid) {       // only the owner rescans
            sims_s[biv] = -1e30f;
            lb = -1e30f; li = -1;
#pragma unroll
            for (int i = 0; i < MM / 256; i++) {
                int m = tid + i * 256;
                float v = sims_s[m];
                if (v > lb) { lb = v; li = m; }
            }
        }
        // no extra sync needed: cross-thread data flows only via wmax/bs_s
    }

    if (tid < DK) {
        int b_ = qidx >> 14;
        int h_ = (qidx >> 10) & 15;
        int s_ = qidx & 1023;
        g_mctx[(long)(b_ * SS + s_) * DD + h_ * 64 + tid] = acc;
    }
}

// ---------------- launch ----------------------------------------------------
extern "C" void kernel_launch(void* const* d_in, const int* in_sizes, int n_in,
                              void* d_out, int out_size)
{
    const float* x        = (const float*)d_in[0];
    const float* Wq       = (const float*)d_in[1];
    const float* bq       = (const float*)d_in[2];
    const float* Wk       = (const float*)d_in[3];
    const float* bk       = (const float*)d_in[4];
    const float* Wv       = (const float*)d_in[5];
    const float* bv       = (const float*)d_in[6];
    const float* Wo       = (const float*)d_in[7];
    const float* bo       = (const float*)d_in[8];
    const float* mem_keys = (const float*)d_in[9];
    const float* mem_vals = (const float*)d_in[10];
    const float* gate     = (const float*)d_in[11];
    float* out = (float*)d_out;

    dim3 gproj(DD / GBN, BSr / GBM);     // 16 x 16

    // QKV projections (scatter to [B,H,S,dk])
    sgemm_nt<0><<<gproj, 256>>>(x, -1, 0, Wq, -1, bq, nullptr, BUF_Q, DD, DD, -1, nullptr);
    sgemm_nt<0><<<gproj, 256>>>(x, -1, 0, Wk, -1, bk, nullptr, BUF_K, DD, DD, -1, nullptr);
    sgemm_nt<0><<<gproj, 256>>>(x, -1, 0, Wv, -1, bv, nullptr, BUF_V, DD, DD, -1, nullptr);

    // causal attention + output projection
    attn_kernel<<<dim3(SS / 4, Bb * HH), 128>>>();
    sgemm_nt<1><<<gproj, 256>>>(nullptr, BUF_ACTX, 0, Wo, -1, bo, nullptr, BUF_APROJ, DD, DD, -1, nullptr);

    // KNN memory path
    normalize_rows<<<MM / 8, 256>>>(mem_keys, -1, BUF_NORMK, MM);
    normalize_rows<<<NQ / 8, 256>>>(nullptr, BUF_Q, BUF_NORMQ, NQ);

    dim3 gsims(MM / GBN, CHUNK / GBM);   // 128 x 16
    for (int ch = 0; ch < NCHUNK; ch++) {
        sgemm_nt<3><<<gsims, 256>>>(nullptr, BUF_NORMQ, (long)ch * CHUNK * DK,
                                    nullptr, BUF_NORMK, nullptr,
                                    nullptr, BUF_SIMS, MM, DK, -1, nullptr);
        topk_kernel<<<CHUNK, 256>>>(mem_vals, ch);
    }

    // memory projection fused with gate combine -> final output
    sgemm_nt<2><<<gproj, 256>>>(nullptr, BUF_MCTX, 0, Wo, -1, bo, out, -1, DD, DD, BUF_APROJ, gate);
}

// round 4
// speedup vs baseline: 1.0356x; 1.0356x over previous
#include <cuda_runtime.h>
#include <math.h>
#include <stdint.h>

// Problem constants (fixed by setup_inputs)
#define Bb    2
#define SS    1024
#define DD    1024
#define HH    16
#define DK    64
#define MM    8192
#define TOPK  32
#define BSr   (Bb*SS)        // 2048 token rows
#define NQ    (Bb*HH*SS)     // 32768 flat queries
#define CHUNK 2048
#define NCHUNK (NQ/CHUNK)    // 16

// ---------------- scratch (device globals; no allocation) ----------------
__device__ float g_q[NQ*DK];        // [B,H,S,dk]
__device__ float g_k[NQ*DK];
__device__ float g_v[NQ*DK];
__device__ float g_actx[BSr*DD];    // attention context [B,S,D]
__device__ float g_aproj[BSr*DD];   // attn_out @ Wo^T + bo
__device__ float g_mctx[BSr*DD];    // memory context [B,S,D]
__device__ float g_normq[NQ*DK];
__device__ float g_normk[MM*DK];
__device__ float g_sims[(long)CHUNK*MM];  // 64MB, reused per chunk (L2-resident)

#define BUF_Q     0
#define BUF_K     1
#define BUF_V     2
#define BUF_ACTX  3
#define BUF_APROJ 4
#define BUF_MCTX  5
#define BUF_NORMQ 6
#define BUF_NORMK 7
#define BUF_SIMS  8

__device__ __forceinline__ float* gbuf(int id) {
    switch (id) {
        case BUF_Q:     return g_q;
        case BUF_K:     return g_k;
        case BUF_V:     return g_v;
        case BUF_ACTX:  return g_actx;
        case BUF_APROJ: return g_aproj;
        case BUF_MCTX:  return g_mctx;
        case BUF_NORMQ: return g_normq;
        case BUF_NORMK: return g_normk;
        case BUF_SIMS:  return g_sims;
    }
    return nullptr;
}

// ============================================================================
// Known-good fp32 SGEMM (Round-1, passed at 6.7e-7) — used for the
// top-k-critical GEMMs: Wq projection and the sims GEMM.
// MODE 0: scatter-store to [B,H,S,dk] layout, + bias
// MODE 3: row-major plain store (sims)
// ============================================================================
#define GBM 128
#define GBN 64
#define GBK 16

template<int MODE>
__global__ __launch_bounds__(256)
void sgemm_nt(const float* __restrict__ Aext, int Aid, long Aoff,
              const float* __restrict__ Wext, int Wid,
              const float* __restrict__ bias,
              float* __restrict__ Cext, int Cid,
              int Nc, int Kd,
              int addid, const float* __restrict__ gatep)
{
    const float* A = (Aext ? Aext : gbuf(Aid)) + Aoff;
    const float* W = Wext ? Wext : gbuf(Wid);
    float* C = Cext ? Cext : gbuf(Cid);

    __shared__ __align__(16) float As[GBK][GBM + 4];
    __shared__ __align__(16) float Ws[GBK][GBN + 4];

    const int tid = threadIdx.x;
    const int rb = blockIdx.y * GBM;
    const int cb = blockIdx.x * GBN;
    const int lr = tid >> 2;            // 0..63
    const int lk = (tid & 3) << 2;      // 0,4,8,12
    const int ty = tid >> 4;            // 0..15
    const int tx = tid & 15;            // 0..15

    float acc[8][4];
#pragma unroll
    for (int i = 0; i < 8; i++)
#pragma unroll
        for (int j = 0; j < 4; j++) acc[i][j] = 0.f;

    for (int kb = 0; kb < Kd; kb += GBK) {
        float4 a0 = *(const float4*)(A + (long)(rb + lr)      * Kd + kb + lk);
        float4 a1 = *(const float4*)(A + (long)(rb + lr + 64) * Kd + kb + lk);
        float4 w0 = *(const float4*)(W + (long)(cb + lr)      * Kd + kb + lk);
        As[lk+0][lr]    = a0.x; As[lk+1][lr]    = a0.y; As[lk+2][lr]    = a0.z; As[lk+3][lr]    = a0.w;
        As[lk+0][lr+64] = a1.x; As[lk+1][lr+64] = a1.y; As[lk+2][lr+64] = a1.z; As[lk+3][lr+64] = a1.w;
        Ws[lk+0][lr]    = w0.x; Ws[lk+1][lr]    = w0.y; Ws[lk+2][lr]    = w0.z; Ws[lk+3][lr]    = w0.w;
        __syncthreads();
#pragma unroll
        for (int kk = 0; kk < GBK; kk++) {
            float4 av0 = *(const float4*)&As[kk][ty * 8];
            float4 av1 = *(const float4*)&As[kk][ty * 8 + 4];
            float4 bv  = *(const float4*)&Ws[kk][tx * 4];
            float a[8] = {av0.x, av0.y, av0.z, av0.w, av1.x, av1.y, av1.z, av1.w};
            float b[4] = {bv.x, bv.y, bv.z, bv.w};
#pragma unroll
            for (int i = 0; i < 8; i++)
#pragma unroll
                for (int j = 0; j < 4; j++)
                    acc[i][j] = fmaf(a[i], b[j], acc[i][j]);
        }
        __syncthreads();
    }

#pragma unroll
    for (int i = 0; i < 8; i++) {
        int r = rb + ty * 8 + i;
#pragma unroll
        for (int j = 0; j < 4; j++) {
            int c = cb + tx * 4 + j;
            float val = acc[i][j];
            if (MODE == 0) {
                int b_ = r >> 10, s_ = r & (SS - 1);
                int h_ = c >> 6,  d_ = c & 63;
                C[(((long)(b_ * HH + h_) * SS + s_) << 6) + d_] = val + bias[c];
            } else {
                C[(long)r * Nc + c] = val;
            }
        }
    }
}

// ============================================================================
// TF32 MMA GEMM (3xTF32 split, err ~1e-7 rel) — used ONLY for tolerant
// GEMMs this round: Wk, Wv, Wo(attn), Wo(mem)+gate. This is the controlled
// test of the engine: if it carries a deterministic bug, this round fails.
// MODE 0: scatter-store to [B,H,S,dk] layout, + bias
// MODE 1: row-major store, + bias
// MODE 2: row-major: out = g*(acc+bias) + (1-g)*add   (g = sigmoid(gate))
// ============================================================================
__device__ __forceinline__ uint32_t f2tf(float x) {
    uint32_t r;
    asm("cvt.rna.tf32.f32 %0, %1;" : "=r"(r) : "f"(x));
    return r;
}

#define MMA_TF32(d, a, b) \
    asm volatile("mma.sync.aligned.m16n8k8.row.col.f32.tf32.tf32.f32 " \
        "{%0,%1,%2,%3},{%4,%5,%6,%7},{%8,%9},{%0,%1,%2,%3};" \
        : "+f"((d)[0]), "+f"((d)[1]), "+f"((d)[2]), "+f"((d)[3]) \
        : "r"((a)[0]), "r"((a)[1]), "r"((a)[2]), "r"((a)[3]), \
          "r"((b)[0]), "r"((b)[1]))

#define BM 128
#define BN 128
#define BK 32
#define SPAD 8

template<int MODE>
__global__ __launch_bounds__(256)
void mma_gemm(const float* __restrict__ Aext, int Aid, long Aoff,
              const float* __restrict__ Wext, int Wid,
              const float* __restrict__ bias,
              float* __restrict__ Cext, int Cid,
              int Nc, int Kd,
              int addid, const float* __restrict__ gatep)
{
    const float* A = (Aext ? Aext : gbuf(Aid)) + Aoff;
    const float* W = Wext ? Wext : gbuf(Wid);
    float* C = Cext ? Cext : gbuf(Cid);

    __shared__ __align__(16) float As[BK][BM + SPAD];
    __shared__ __align__(16) float Bs[BK][BN + SPAD];

    const int tid  = threadIdx.x;
    const int rb   = blockIdx.y * BM;
    const int cb   = blockIdx.x * BN;
    const int wid  = tid >> 5;
    const int lane = tid & 31;
    const int wm   = (wid >> 2) * 64;    // warp row offset (0,64)
    const int wn   = (wid & 3) * 32;     // warp col offset (0,32,64,96)
    const int g    = lane >> 2;          // groupID 0..7
    const int tg   = lane & 3;           // thread-in-group 0..3

    const int lr = tid >> 1;             // 0..127 (row in tile)
    const int lk = (tid & 1) * 16;       // k offset 0 or 16

    float acc[4][4][4];
#pragma unroll
    for (int mi = 0; mi < 4; mi++)
#pragma unroll
        for (int ni = 0; ni < 4; ni++)
#pragma unroll
            for (int r = 0; r < 4; r++) acc[mi][ni][r] = 0.f;

    float4 aR[4], bR[4];
    {
        const float* Ap = A + (long)(rb + lr) * Kd + lk;
        const float* Wp = W + (long)(cb + lr) * Kd + lk;
#pragma unroll
        for (int j = 0; j < 4; j++) {
            aR[j] = *(const float4*)(Ap + j * 4);
            bR[j] = *(const float4*)(Wp + j * 4);
        }
    }

    for (int kb = 0; kb < Kd; kb += BK) {
#pragma unroll
        for (int j = 0; j < 4; j++) {
            As[lk + j*4 + 0][lr] = aR[j].x; As[lk + j*4 + 1][lr] = aR[j].y;
            As[lk + j*4 + 2][lr] = aR[j].z; As[lk + j*4 + 3][lr] = aR[j].w;
            Bs[lk + j*4 + 0][lr] = bR[j].x; Bs[lk + j*4 + 1][lr] = bR[j].y;
            Bs[lk + j*4 + 2][lr] = bR[j].z; Bs[lk + j*4 + 3][lr] = bR[j].w;
        }
        __syncthreads();

        if (kb + BK < Kd) {
            const float* Ap = A + (long)(rb + lr) * Kd + kb + BK + lk;
            const float* Wp = W + (long)(cb + lr) * Kd + kb + BK + lk;
#pragma unroll
            for (int j = 0; j < 4; j++) {
                aR[j] = *(const float4*)(Ap + j * 4);
                bR[j] = *(const float4*)(Wp + j * 4);
            }
        }

#pragma unroll
        for (int ks = 0; ks < 4; ks++) {
            const int k0 = ks * 8;
            uint32_t ah[4][4], al[4][4];
#pragma unroll
            for (int mi = 0; mi < 4; mi++) {
                const int m = wm + mi * 16 + g;
                float x0 = As[k0 + tg][m];
                float x1 = As[k0 + tg][m + 8];
                float x2 = As[k0 + tg + 4][m];
                float x3 = As[k0 + tg + 4][m + 8];
                ah[mi][0] = f2tf(x0); al[mi][0] = f2tf(x0 - __uint_as_float(ah[mi][0]));
                ah[mi][1] = f2tf(x1); al[mi][1] = f2tf(x1 - __uint_as_float(ah[mi][1]));
                ah[mi][2] = f2tf(x2); al[mi][2] = f2tf(x2 - __uint_as_float(ah[mi][2]));
                ah[mi][3] = f2tf(x3); al[mi][3] = f2tf(x3 - __uint_as_float(ah[mi][3]));
            }
            uint32_t bh[4][2], bl[4][2];
#pragma unroll
            for (int ni = 0; ni < 4; ni++) {
                const int n = wn + ni * 8 + g;
                float y0 = Bs[k0 + tg][n];
                float y1 = Bs[k0 + tg + 4][n];
                bh[ni][0] = f2tf(y0); bl[ni][0] = f2tf(y0 - __uint_as_float(bh[ni][0]));
                bh[ni][1] = f2tf(y1); bl[ni][1] = f2tf(y1 - __uint_as_float(bh[ni][1]));
            }
#pragma unroll
            for (int mi = 0; mi < 4; mi++)
#pragma unroll
                for (int ni = 0; ni < 4; ni++) {
                    MMA_TF32(acc[mi][ni], ah[mi], bh[ni]);
                    MMA_TF32(acc[mi][ni], ah[mi], bl[ni]);
                    MMA_TF32(acc[mi][ni], al[mi], bh[ni]);
                }
        }
        __syncthreads();
    }

    float gt = 0.f;
    if (MODE == 2) gt = 1.f / (1.f + __expf(-gatep[0]));
    const float* add = (MODE == 2) ? gbuf(addid) : nullptr;

#pragma unroll
    for (int mi = 0; mi < 4; mi++) {
#pragma unroll
        for (int ni = 0; ni < 4; ni++) {
#pragma unroll
            for (int r = 0; r < 4; r++) {
                const int row = rb + wm + mi * 16 + g + ((r >> 1) ? 8 : 0);
                const int col = cb + wn + ni * 8 + tg * 2 + (r & 1);
                float val = acc[mi][ni][r];
                if (MODE == 0) {
                    int b_ = row >> 10, s_ = row & (SS - 1);
                    int h_ = col >> 6,  d_ = col & 63;
                    C[(((long)(b_ * HH + h_) * SS + s_) << 6) + d_] = val + bias[col];
                } else if (MODE == 1) {
                    C[(long)row * Nc + col] = val + bias[col];
                } else if (MODE == 2) {
                    C[(long)row * Nc + col] =
                        gt * (val + bias[col]) + (1.f - gt) * add[(long)row * Nc + col];
                }
            }
        }
    }
}

// ---------------- causal attention: 4 queries per block (Round-1, known good)
__global__ __launch_bounds__(128)
void attn_kernel()
{
    const int bh = blockIdx.y;           // 0..31
    const int s0 = blockIdx.x * 4;
    const int b_ = bh >> 4, h_ = bh & 15;
    const int tid = threadIdx.x;
    const int Lmax = s0 + 4;

    __shared__ __align__(16) float4 sc[SS];      // per-key probs for q0..q3
    __shared__ __align__(16) float  qs[4][DK];
    __shared__ float invs[4];
    __shared__ float pacc[4][DK];

    // phase 1: load 4 query rows
    for (int idx = tid; idx < 4 * DK; idx += 128) {
        int i = idx >> 6, d = idx & 63;
        qs[i][d] = g_q[(((long)bh * SS + s0 + i) << 6) + d];
    }
    __syncthreads();

    // phase 2: scores (each thread owns keys j = tid, tid+128, ...)
    const float scale = 0.125f;  // 1/sqrt(64)
    for (int j = tid; j < Lmax; j += 128) {
        const float4* kr = (const float4*)(g_k + (((long)bh * SS + j) << 6));
        float d0 = 0.f, d1 = 0.f, d2 = 0.f, d3 = 0.f;
#pragma unroll
        for (int c4 = 0; c4 < 16; c4++) {
            float4 kv = kr[c4];
            float4 q0 = *(const float4*)&qs[0][c4 * 4];
            float4 q1 = *(const float4*)&qs[1][c4 * 4];
            float4 q2 = *(const float4*)&qs[2][c4 * 4];
            float4 q3 = *(const float4*)&qs[3][c4 * 4];
            d0 += kv.x*q0.x + kv.y*q0.y + kv.z*q0.z + kv.w*q0.w;
            d1 += kv.x*q1.x + kv.y*q1.y + kv.z*q1.z + kv.w*q1.w;
            d2 += kv.x*q2.x + kv.y*q2.y + kv.z*q2.z + kv.w*q2.w;
            d3 += kv.x*q3.x + kv.y*q3.y + kv.z*q3.z + kv.w*q3.w;
        }
        sc[j] = make_float4(d0 * scale, d1 * scale, d2 * scale, d3 * scale);
    }
    __syncthreads();

    // phase 3: warp w does softmax for query w (causal length L = s0+w+1)
    {
        const int w = tid >> 5, lane = tid & 31;
        const int L = s0 + w + 1;
        float m = -1e30f;
        for (int j = lane; j < L; j += 32)
            m = fmaxf(m, ((const float*)&sc[j])[w]);
#pragma unroll
        for (int off = 16; off; off >>= 1)
            m = fmaxf(m, __shfl_xor_sync(0xffffffffu, m, off));
        float ssum = 0.f;
        for (int j = lane; j < L; j += 32) {
            float* p = &((float*)&sc[j])[w];
            float e = __expf(*p - m);
            *p = e;
            ssum += e;
        }
#pragma unroll
        for (int off = 16; off; off >>= 1)
            ssum += __shfl_xor_sync(0xffffffffu, ssum, off);
        if (lane == 0) invs[w] = 1.f / ssum;
        for (int j = L + lane; j < Lmax; j += 32)   // zero masked tail
            ((float*)&sc[j])[w] = 0.f;
    }
    __syncthreads();

    // phase 4: P @ V (thread = (half, d); lanes coalesced over d)
    const int d = tid & 63, half = tid >> 6;
    float a0 = 0.f, a1 = 0.f, a2 = 0.f, a3 = 0.f;
    for (int j = half; j < Lmax; j += 2) {
        float vv = g_v[(((long)bh * SS + j) << 6) + d];
        float4 p = sc[j];
        a0 = fmaf(p.x, vv, a0);
        a1 = fmaf(p.y, vv, a1);
        a2 = fmaf(p.z, vv, a2);
        a3 = fmaf(p.w, vv, a3);
    }
    if (half == 1) { pacc[0][d] = a0; pacc[1][d] = a1; pacc[2][d] = a2; pacc[3][d] = a3; }
    __syncthreads();
    if (half == 0) {
        a0 += pacc[0][d]; a1 += pacc[1][d]; a2 += pacc[2][d]; a3 += pacc[3][d];
        long base = ((long)(b_ * SS + s0)) * DD + h_ * 64 + d;
        g_actx[base]          = a0 * invs[0];
        g_actx[base +   DD]   = a1 * invs[1];
        g_actx[base + 2*DD]   = a2 * invs[2];
        g_actx[base + 3*DD]   = a3 * invs[3];
    }
}

// ---------------- row L2-normalization: v / (||v|| + 1e-8) -----------------
__global__ __launch_bounds__(256)
void normalize_rows(const float* __restrict__ ext, int srcid, int dstid, int rows)
{
    const float* src = ext ? ext : gbuf(srcid);
    float* dst = gbuf(dstid);
    int row = blockIdx.x * 8 + (threadIdx.x >> 5);
    int lane = threadIdx.x & 31;
    if (row >= rows) return;
    float e0 = src[(long)row * DK + lane];
    float e1 = src[(long)row * DK + lane + 32];
    float ss = e0 * e0 + e1 * e1;
#pragma unroll
    for (int off = 16; off; off >>= 1)
        ss += __shfl_xor_sync(0xffffffffu, ss, off);
    float sc = 1.f / (sqrtf(ss) + 1e-8f);
    dst[(long)row * DK + lane]      = e0 * sc;
    dst[(long)row * DK + lane + 32] = e1 * sc;
}

// ---------------- top-K selection + weighted gather ------------------------
__global__ __launch_bounds__(256)
void topk_kernel(const float* __restrict__ mem_vals, int chunk)
{
    const int qloc = blockIdx.x;
    const int qidx = chunk * CHUNK + qloc;
    const int tid = threadIdx.x;
    const int lane = tid & 31, wid = tid >> 5;

    __shared__ __align__(16) float sims_s[MM];   // 32KB
    __shared__ float wmax[8];
    __shared__ int   widx[8];
    __shared__ float bs_s;
    __shared__ int   bi_s;

    const float4* src = (const float4*)(g_sims + (long)qloc * MM);
    for (int m4 = tid; m4 < MM / 4; m4 += 256)
        ((float4*)sims_s)[m4] = src[m4];
    __syncthreads();

    float lb = -1e30f; int li = -1;
#pragma unroll
    for (int i = 0; i < MM / 256; i++) {
        int m = tid + i * 256;
        float v = sims_s[m];
        if (v > lb) { lb = v; li = m; }
    }

    float acc = 0.f;
    for (int t = 0; t < TOPK; t++) {
        float bv = lb; int bi = li;
#pragma unroll
        for (int off = 16; off; off >>= 1) {
            float ov = __shfl_xor_sync(0xffffffffu, bv, off);
            int   oi = __shfl_xor_sync(0xffffffffu, bi, off);
            if (ov > bv || (ov == bv && oi < bi)) { bv = ov; bi = oi; }
        }
        if (lane == 0) { wmax[wid] = bv; widx[wid] = bi; }
        __syncthreads();
        if (wid == 0) {
            float v2 = (lane < 8) ? wmax[lane] : -1e30f;
            int   i2 = (lane < 8) ? widx[lane] : 0x7fffffff;
#pragma unroll
            for (int off = 4; off; off >>= 1) {
                float ov = __shfl_xor_sync(0xffffffffu, v2, off);
                int   oi = __shfl_xor_sync(0xffffffffu, i2, off);
                if (ov > v2 || (ov == v2 && oi < i2)) { v2 = ov; i2 = oi; }
            }
            if (lane == 0) { bs_s = v2; bi_s = i2; }
        }
        __syncthreads();
        float bsv = bs_s; int biv = bi_s;
        if (tid < DK)
            acc = fmaf(bsv, mem_vals[(long)biv * DK + tid], acc);
        if ((biv & 255) == tid) {       // owner invalidates and rescans
            sims_s[biv] = -1e30f;
            lb = -1e30f; li = -1;
#pragma unroll
            for (int i = 0; i < MM / 256; i++) {
                int m = tid + i * 256;
                float v = sims_s[m];
                if (v > lb) { lb = v; li = m; }
            }
        }
    }

    if (tid < DK) {
        int b_ = qidx >> 14;
        int h_ = (qidx >> 10) & 15;
        int s_ = qidx & 1023;
        g_mctx[(long)(b_ * SS + s_) * DD + h_ * 64 + tid] = acc;
    }
}

// ---------------- launch ----------------------------------------------------
extern "C" void kernel_launch(void* const* d_in, const int* in_sizes, int n_in,
                              void* d_out, int out_size)
{
    const float* x        = (const float*)d_in[0];
    const float* Wq       = (const float*)d_in[1];
    const float* bq       = (const float*)d_in[2];
    const float* Wk       = (const float*)d_in[3];
    const float* bk       = (const float*)d_in[4];
    const float* Wv       = (const float*)d_in[5];
    const float* bv       = (const float*)d_in[6];
    const float* Wo       = (const float*)d_in[7];
    const float* bo       = (const float*)d_in[8];
    const float* mem_keys = (const float*)d_in[9];
    const float* mem_vals = (const float*)d_in[10];
    const float* gate     = (const float*)d_in[11];
    float* out = (float*)d_out;

    dim3 gproj_s(DD / GBN, BSr / GBM);   // fp32 sgemm grid: 16 x 16
    dim3 gproj_m(DD / BN, BSr / BM);     // mma grid: 8 x 16

    // Wq: top-k-critical -> known-good fp32 sgemm
    sgemm_nt<0><<<gproj_s, 256>>>(x, -1, 0, Wq, -1, bq, nullptr, BUF_Q, DD, DD, -1, nullptr);
    // Wk, Wv: tolerant -> tensor-pipe MMA (engine validation experiment)
    mma_gemm<0><<<gproj_m, 256>>>(x, -1, 0, Wk, -1, bk, nullptr, BUF_K, DD, DD, -1, nullptr);
    mma_gemm<0><<<gproj_m, 256>>>(x, -1, 0, Wv, -1, bv, nullptr, BUF_V, DD, DD, -1, nullptr);

    // causal attention (Round-1 kernel) + output projection (MMA)
    attn_kernel<<<dim3(SS / 4, Bb * HH), 128>>>();
    mma_gemm<1><<<gproj_m, 256>>>(nullptr, BUF_ACTX, 0, Wo, -1, bo, nullptr, BUF_APROJ, DD, DD, -1, nullptr);

    // KNN memory path (all Round-1 known-good components)
    normalize_rows<<<MM / 8, 256>>>(mem_keys, -1, BUF_NORMK, MM);
    normalize_rows<<<NQ / 8, 256>>>(nullptr, BUF_Q, BUF_NORMQ, NQ);

    dim3 gsims(MM / GBN, CHUNK / GBM);   // 128 x 16
    for (int ch = 0; ch < NCHUNK; ch++) {
        sgemm_nt<3><<<gsims, 256>>>(nullptr, BUF_NORMQ, (long)ch * CHUNK * DK,
                                    nullptr, BUF_NORMK, nullptr,
                                    nullptr, BUF_SIMS, MM, DK, -1, nullptr);
        topk_kernel<<<CHUNK, 256>>>(mem_vals, ch);
    }

    // memory projection fused with gate combine -> final output (MMA)
    mma_gemm<2><<<gproj_m, 256>>>(nullptr, BUF_MCTX, 0, Wo, -1, bo, out, -1, DD, DD, BUF_APROJ, gate);
}